// round 8
// baseline (speedup 1.0000x reference)
#include <cuda_runtime.h>
#include <cuda_bf16.h>
#include <math.h>

// Spectral evaluation of the reference power iteration: ONE warp, one launch.
//
//   out = pref * sum_{k odd} (-1)^((k-1)/2) * lam_k^T * sin(s k pi/1024)
//   lam_k = pmid + 2 sqrt(p1 p2) cos(k pi/1024)
//   pref  = (2/1024) * (p2/p1)^{(z-s)/2},  z = IDX_Z = 512
//
// Even-k modes vanish (sin(k pi/2) = 0). Screen: chord bound gives integer
// cutoff kmax with T*eps_k <= ~197 for survivors; eps_k = 1-lam_k is computed
// cancellation-free so f32 gives exp(T log lam) rel err ~4e-5. Single warp:
// no barrier, no smem, 16-deep k-loop (real inputs exit after 2 iterations).
// Prefactor is computed on lane 31 concurrently and merged after the reduce.

__global__ __launch_bounds__(32, 1)
void spectral_fused(const float* __restrict__ muP,
                    const int* __restrict__ TP,
                    const int* __restrict__ sP,
                    float* __restrict__ out) {
    const int tid = (int)threadIdx.x;
    const int T   = TP[0];
    const int s   = sP[0];

    // ---- f32 coefficients: replicate the reference's float32 sequence exactly.
    // DX = 2^-9 exactly -> /DX, /DX^2 are exact scalings.
    const float mu   = muP[0];
    const float m1   = mu * 2e-6f;
    const float m2   = m1 * m1 + 2e-6f;
    const float af   = m2 * 262144.0f;   // m2 / DX^2
    const float bf   = m1 * 512.0f;      // m1 / DX
    const float p1   = (af + bf) * 0.5f;
    const float p2   = (af - bf) * 0.5f;
    const float pmid = 1.0f - p1 - p2;

    // ---- Cancellation-free spectral constants, f32.
    const float sqf   = sqrtf(p1 * p2);                         // sqrt(p1 p2)
    const float diffc = (float)((double)p1 - (double)p2);       // exactly rounded
    const float d2f   = diffc * diffc / (p1 + p2 + 2.0f * sqf); // (sqrt p1 - sqrt p2)^2
    const float sq4f  = 4.0f * sqf;
    // pmid f32 rounding residual, exact in double.
    const float deltaf = (float)((1.0 - (double)pmid) - ((double)p1 + (double)p2));

    // ---- Screening cutoff (chord bound sin(pi y) >= 2y for y <= 1/2):
    // survivors satisfy k <= 1024*sqrt((80/T - d2)/(4 sq)).
    const float thr = 80.0f / (float)T;
    const float S2  = (thr - d2f) / sq4f;
    float kmaxf = (S2 > 0.0f) ? 1024.0f * sqrtf(S2) : 0.0f;
    const int kmax = (int)fminf(fmaxf(kmaxf * 1.0005f + 2.0f, 3.0f), 1023.0f);

    const bool s_ok = (s >= 1 && s <= 1023);
    const float Tf  = (float)T;

    // ---- Prefactor on lane 31, concurrent with mode math on lanes 0..30.
    // pref = exp((z-s)*atanh((p2-p1)/(p2+p1))) * 2/1024,  z = 512.
    float pref = 0.0f;
    if (tid == 31) {
        float un = -diffc;                 // p2 - p1, exactly rounded
        float u  = un / (p2 + p1);
        float u2 = u * u;
        float S  = u * fmaf(u2, fmaf(u2, fmaf(u2, 0.14285715f, 0.2f),
                                     0.33333334f), 1.0f);
        pref = __expf((float)(512 - s) * S) * (2.0f / 1024.0f);
    }

    // ---- Mode loop: k = 2*(tid + 32*j) + 1 covers all odd k in 1..1023.
    double acc = 0.0;
    if (s_ok) {
        #pragma unroll 2
        for (int j = 0; j < 16; j++) {
            const int i = tid + 32 * j;
            const int k = 2 * i + 1;
            if (k > kmax) break;

            // eps_k = 1 - lam_k, cancellation-free, f32.
            float spf = sinpif((float)k * (1.0f / 2048.0f));
            float eps = fmaf(sq4f * spf, spf, d2f) + deltaf;

            float term;
            if (eps <= 0.03f) {
                // T*log1p(-eps) = -T*eps*(1 + e/2 + e^2/3 + e^3/4 + e^4/5)
                float q = fmaf(eps, fmaf(eps, fmaf(eps, fmaf(eps, 0.2f, 0.25f),
                                                   0.33333334f), 0.5f), 1.0f);
                term = __expf(-Tf * eps * q);
            } else {
                // Generic fallback (small T only; never taken for T=10000).
                double lam = 1.0 - (double)eps;
                double al  = fabs(lam);
                double w   = (al > 0.0) ? (double)T * log(al) : -1e12;
                double td  = (w > -745.0) ? exp(w) : 0.0;
                if (lam < 0.0 && (T & 1)) td = -td;
                term = (float)td;
            }

            // sin(s k pi/1024): exact multiple of 2^-10, sinpif reduces exactly.
            float ss  = sinpif((float)((s * k) & 2047) * (1.0f / 1024.0f));
            float sgn = (i & 1) ? -1.0f : 1.0f;    // (-1)^((k-1)/2)
            acc += (double)(term * ss * sgn);
        }
    }

    // ---- Single-warp reduction (double), then merge lane-31 prefactor.
    #pragma unroll
    for (int o = 16; o > 0; o >>= 1)
        acc += __shfl_down_sync(0xffffffffu, acc, o);

    float pref0 = __shfl_sync(0xffffffffu, pref, 31);
    if (tid == 0)
        out[0] = (float)acc * pref0;
}

extern "C" void kernel_launch(void* const* d_in, const int* in_sizes, int n_in,
                              void* d_out, int out_size) {
    const float* mu    = (const float*)d_in[0];
    const int*   idx_T = (const int*)d_in[1];
    const int*   idx_s = (const int*)d_in[2];
    float*       out   = (float*)d_out;

    spectral_fused<<<1, 32>>>(mu, idx_T, idx_s, out);
}

// round 9
// speedup vs baseline: 1.0435x; 1.0435x over previous
#include <cuda_runtime.h>
#include <cuda_bf16.h>
#include <math.h>

// Spectral evaluation of the reference power iteration: ONE warp, one launch,
// all-FP32 critical path (double only for the exact pmid rounding residual,
// computed concurrently with the f32 preamble via ILP).
//
//   out = pref * sum_{k odd} (-1)^((k-1)/2) * lam_k^T * sin(s k pi/1024)
//   lam_k = pmid + 2 sqrt(p1 p2) cos(k pi/1024)
//   pref  = (2/1024) * (p2/p1)^{(z-s)/2},  z = IDX_Z = 512
//
// Even-k modes vanish (sin(k pi/2) = 0). eps_k = 1 - lam_k is computed
// cancellation-free so f32 keeps exp(T log lam) abs-exponent error <= ~4e-5.
// Loop exit is a warp-UNIFORM chord-bound test on the base k of the warp
// (eps >= 4*sqrt(p1p2)*(k/1024)^2 + d2, monotone in k); lanes past the cutoff
// simply compute __expf(-large) -> 0, so there is no per-lane branching.

__global__ __launch_bounds__(32, 1)
void spectral_fused(const float* __restrict__ muP,
                    const int* __restrict__ TP,
                    const int* __restrict__ sP,
                    float* __restrict__ out) {
    const int tid = (int)threadIdx.x;
    const int T   = TP[0];
    const int s   = sP[0];

    // ---- f32 coefficients: replicate the reference's float32 sequence exactly.
    // DX = 2^-9 exactly -> /DX, /DX^2 are exact scalings.
    const float mu   = muP[0];
    const float m1   = mu * 2e-6f;
    const float m2   = m1 * m1 + 2e-6f;
    const float af   = m2 * 262144.0f;   // m2 / DX^2
    const float bf   = m1 * 512.0f;      // m1 / DX
    const float p1   = (af + bf) * 0.5f;
    const float p2   = (af - bf) * 0.5f;
    const float pmid = 1.0f - p1 - p2;

    // ---- Cancellation-free spectral constants, f32 fast ops.
    const float x    = fmaxf(p1 * p2, 1e-30f);
    const float sqf  = x * rsqrtf(x);                            // sqrt(p1 p2), ~2e-7 rel
    const float diffc = (float)((double)p1 - (double)p2);        // exactly rounded
    const float d2f  = __fdividef(diffc * diffc, p1 + p2 + 2.0f * sqf); // (sqrt p1 - sqrt p2)^2
    const float sq4f = 4.0f * sqf;
    // pmid f32 rounding residual, exact in double (ILP-overlapped, off chain).
    const float deltaf = (float)((1.0 - (double)pmid) - ((double)p1 + (double)p2));

    const bool  s_ok = (s >= 1 && s <= 1023);
    const float Tf   = (float)T;

    // ---- Prefactor (all lanes compute; lane-31 value used).
    // pref = exp((z-s)*atanh((p2-p1)/(p2+p1))) * 2/1024,  z = 512.
    const float u  = __fdividef(-diffc, p2 + p1);
    const float u2 = u * u;
    const float S  = u * fmaf(u2, fmaf(u2, fmaf(u2, 0.14285715f, 0.2f),
                                       0.33333334f), 1.0f);
    const float pref = __expf((float)(512 - s) * S) * (2.0f / 1024.0f);

    // ---- Mode loop: k = 2*(tid + 32*j) + 1 covers all odd k in 1..1023.
    float acc = 0.0f;
    if (s_ok) {
        #pragma unroll 2
        for (int j = 0; j < 16; j++) {
            // Warp-uniform break: chord lower bound at this warp's base k.
            const int   kbase = 64 * j + 1;
            const float ylb   = (float)kbase * (1.0f / 1024.0f);
            const float epslb = fmaf(sq4f * ylb, ylb, d2f);
            if (Tf * epslb > 80.0f) break;

            const int k = 2 * (tid + 32 * j) + 1;

            // eps_k = 1 - lam_k, cancellation-free, f32.
            const float spf = sinpif((float)k * (1.0f / 2048.0f));
            const float eps = fmaf(sq4f * spf, spf, d2f) + deltaf;

            float term;
            if (eps <= 0.03f) {
                // T*log1p(-eps) = -T*eps*(1 + e/2 + e^2/3 + e^3/4 + e^4/5)
                const float q = fmaf(eps, fmaf(eps, fmaf(eps, fmaf(eps, 0.2f, 0.25f),
                                                         0.33333334f), 0.5f), 1.0f);
                term = __expf(-Tf * eps * q);   // underflows to 0 for dead lanes
            } else {
                // Generic fallback (small T only; never taken for T=10000).
                const float lam = 1.0f - eps;
                const float al  = fabsf(lam);
                float w = (al > 0.0f) ? Tf * __logf(al) : -1e12f;
                term = (w > -87.0f) ? __expf(w) : 0.0f;
                if (lam < 0.0f && (T & 1)) term = -term;
            }

            // sin(s k pi/1024): exact multiple of 2^-10, sinpif reduces exactly.
            const float ss  = sinpif((float)((s * k) & 2047) * (1.0f / 1024.0f));
            const float sgn = ((tid ^ j) & 1) ? -1.0f : 1.0f;  // (-1)^((k-1)/2), (k-1)/2 = tid+32j
            acc = fmaf(term * ss, sgn, acc);
        }
    }

    // ---- Single-warp f32 reduction, then apply prefactor.
    #pragma unroll
    for (int o = 16; o > 0; o >>= 1)
        acc += __shfl_down_sync(0xffffffffu, acc, o);

    const float pref0 = __shfl_sync(0xffffffffu, pref, 31);
    if (tid == 0)
        out[0] = acc * pref0;
}

extern "C" void kernel_launch(void* const* d_in, const int* in_sizes, int n_in,
                              void* d_out, int out_size) {
    const float* mu    = (const float*)d_in[0];
    const int*   idx_T = (const int*)d_in[1];
    const int*   idx_s = (const int*)d_in[2];
    float*       out   = (float*)d_out;

    spectral_fused<<<1, 32>>>(mu, idx_T, idx_s, out);
}

// round 11
// speedup vs baseline: 1.0588x; 1.0147x over previous
#include <cuda_runtime.h>
#include <cuda_bf16.h>
#include <math.h>

// Spectral evaluation of the reference power iteration: ONE warp, one launch,
// all-FP32 critical path. (sm_103 has no redux.sync.add.f32 — R10 compile
// error — so the warp sum is the classic 5-round shfl tree.)
//
//   out = pref * sum_{k odd} (-1)^((k-1)/2) * lam_k^T * sin(s k pi/1024)
//   lam_k = pmid + 2 sqrt(p1 p2) cos(k pi/1024)
//   pref  = (2/1024) * (p2/p1)^{(z-s)/2},  z = IDX_Z = 512
//
// Even-k modes vanish (sin(k pi/2) = 0). eps_k = 1 - lam_k is computed
// cancellation-free so f32 keeps the exponent w = T log(lam) accurate to
// ~4e-5 absolute. Iteration 0 (k <= 63) is peeled and unconditional; later
// iterations gate on a warp-uniform chord-bound test. Lanes past the true
// cutoff evaluate __expf(-large) -> 0 (no per-lane branching).

__device__ __forceinline__ float mode_term(int i, int s, float Tf,
                                           float sq4f, float d2f, float deltaf,
                                           int T) {
    const int k = 2 * i + 1;

    // eps_k = 1 - lam_k, cancellation-free, f32.
    const float spf = sinpif((float)k * (1.0f / 2048.0f));
    const float eps = fmaf(sq4f * spf, spf, d2f) + deltaf;

    float term;
    if (eps <= 0.03f) {
        // T*log1p(-eps) = -T*eps*(1 + e/2 + e^2/3 + e^3/4 + e^4/5)
        const float q = fmaf(eps, fmaf(eps, fmaf(eps, fmaf(eps, 0.2f, 0.25f),
                                                 0.33333334f), 0.5f), 1.0f);
        term = __expf(-Tf * eps * q);   // underflows to 0 for dead lanes
    } else {
        // Generic fallback (small T only; never taken for T=10000 inputs).
        const float lam = 1.0f - eps;
        const float al  = fabsf(lam);
        float w = (al > 0.0f) ? Tf * __logf(al) : -1e12f;
        term = (w > -87.0f) ? __expf(w) : 0.0f;
        if (lam < 0.0f && (T & 1)) term = -term;
    }

    // sin(s k pi/1024): exact multiple of 2^-10, sinpif reduces exactly.
    // Fold sign (-1)^((k-1)/2) = (-1)^i into ss via sign-bit XOR.
    float ss = sinpif((float)((s * k) & 2047) * (1.0f / 1024.0f));
    ss = __int_as_float(__float_as_int(ss) ^ ((i & 1) << 31));
    return term * ss;
}

__global__ __launch_bounds__(32, 1)
void spectral_fused(const float* __restrict__ muP,
                    const int* __restrict__ TP,
                    const int* __restrict__ sP,
                    float* __restrict__ out) {
    const int tid = (int)threadIdx.x;
    const int T   = TP[0];
    const int s   = sP[0];

    // ---- f32 coefficients: replicate the reference's float32 sequence exactly.
    // DX = 2^-9 exactly -> /DX, /DX^2 are exact scalings.
    const float mu   = muP[0];
    const float m1   = mu * 2e-6f;
    const float m2   = m1 * m1 + 2e-6f;
    const float af   = m2 * 262144.0f;   // m2 / DX^2
    const float bf   = m1 * 512.0f;      // m1 / DX
    const float p1   = (af + bf) * 0.5f;
    const float p2   = (af - bf) * 0.5f;
    const float pmid = 1.0f - p1 - p2;

    // ---- Cancellation-free spectral constants, f32 fast ops.
    const float x     = fmaxf(p1 * p2, 1e-30f);
    const float sqf   = x * rsqrtf(x);                           // sqrt(p1 p2)
    const float diffc = (float)((double)p1 - (double)p2);        // exactly rounded
    const float d2f   = __fdividef(diffc * diffc, p1 + p2 + 2.0f * sqf);
    const float sq4f  = 4.0f * sqf;
    // pmid f32 rounding residual, exact in double (off-chain via ILP).
    const float deltaf = (float)((1.0 - (double)pmid) - ((double)p1 + (double)p2));

    const bool  s_ok = (s >= 1 && s <= 1023);
    const float Tf   = (float)T;

    // ---- Prefactor (each lane computes its own copy; lane 0's is used).
    // pref = exp((z-s)*atanh((p2-p1)/(p2+p1))) * 2/1024,  z = 512.
    const float u  = __fdividef(-diffc, p2 + p1);
    const float u2 = u * u;
    const float S  = u * fmaf(u2, fmaf(u2, fmaf(u2, 0.14285715f, 0.2f),
                                       0.33333334f), 1.0f);
    const float pref = __expf((float)(512 - s) * S) * (2.0f / 1024.0f);

    // ---- Mode sum: k = 2*(tid + 32*j) + 1 covers all odd k in 1..1023.
    float acc = 0.0f;
    if (s_ok) {
        // Iteration 0 (k = 1..63): unconditional. If even k=1 fails the
        // screen, every term underflows to 0 — still correct.
        acc = mode_term(tid, s, Tf, sq4f, d2f, deltaf, T);

        // Iterations 1..15: warp-uniform chord-bound gate on the base k.
        for (int j = 1; j < 16; j++) {
            const float ylb   = (float)(64 * j + 1) * (1.0f / 1024.0f);
            const float epslb = fmaf(sq4f * ylb, ylb, d2f);
            if (Tf * epslb > 80.0f) break;
            acc += mode_term(tid + 32 * j, s, Tf, sq4f, d2f, deltaf, T);
        }
    }

    // ---- Warp reduction (5-round shfl tree) + store.
    #pragma unroll
    for (int o = 16; o > 0; o >>= 1)
        acc += __shfl_down_sync(0xffffffffu, acc, o);

    if (tid == 0)
        out[0] = acc * pref;
}

extern "C" void kernel_launch(void* const* d_in, const int* in_sizes, int n_in,
                              void* d_out, int out_size) {
    const float* mu    = (const float*)d_in[0];
    const int*   idx_T = (const int*)d_in[1];
    const int*   idx_s = (const int*)d_in[2];
    float*       out   = (float*)d_out;

    spectral_fused<<<1, 32>>>(mu, idx_T, idx_s, out);
}